// round 3
// baseline (speedup 1.0000x reference)
#include <cuda_runtime.h>
#include <cstdint>

// Problem constants
#define BATCH 1024
#define SEQ   512
#define NF    64
#define H     128
#define G4    512
#define NOUT  128

// Main kernel config
#define M        8            // batch rows per CTA
#define NCTA     128          // 1024/8
#define NTHR     512
#define RRES     82           // W_hh k-rows resident in smem (rest streamed from L2)
#define GBPAD    9
#define HDPAD    20           // hd row stride in floats (dup pairs, 16B-aligned rows)

// main smem layout (floats)
#define OFF_WSM   0
#define OFF_XB    (RRES * G4)                    // [2][M][G4]
#define OFF_HD    (OFF_XB + 2 * M * G4)          // [H][HDPAD]
#define OFF_GBUF  (OFF_HD + H * HDPAD)           // [G4][GBPAD]
#define SMEM_FLOATS (OFF_GBUF + G4 * GBPAD)      // 57344
#define SMEM_BYTES  (SMEM_FLOATS * 4)            // 229376

// prefix kernel config
#define PF_NCTA   1024
#define PF_ROWS   512                            // (b,t) rows per CTA
#define PF_XDPAD  20
#define PF_SMEM_FLOATS (NF * G4 + NF * PF_XDPAD) // 32768 + 1280
#define PF_SMEM_BYTES  (PF_SMEM_FLOATS * 4)      // 136192

typedef unsigned long long ull;

// transposed weights + giant xg scratch
__device__ float g_WihT[NF * G4];                  // [f][c]
__device__ float g_WhhT[H * G4];                   // [k][c]
__device__ float g_xg[(size_t)SEQ * BATCH * G4];   // [t][b][c]  (1 GB)

// ---------------- packed f32x2 helpers ----------------
__device__ __forceinline__ void ffma2(ull& acc, ull a, ull b) {
    asm("fma.rn.f32x2 %0, %1, %2, %0;" : "+l"(acc) : "l"(a), "l"(b));
}
__device__ __forceinline__ ull pack2(float lo, float hi) {
    ull r; asm("mov.b64 %0, {%1, %2};" : "=l"(r) : "f"(lo), "f"(hi)); return r;
}
__device__ __forceinline__ void unpack2(ull v, float& lo, float& hi) {
    asm("mov.b64 {%0, %1}, %2;" : "=f"(lo), "=f"(hi) : "l"(v));
}

// ---------------- activations ----------------
__device__ __forceinline__ float ex2f(float x) { float r; asm("ex2.approx.f32 %0, %1;" : "=f"(r) : "f"(x)); return r; }
__device__ __forceinline__ float rcpf(float x) { float r; asm("rcp.approx.f32 %0, %1;" : "=f"(r) : "f"(x)); return r; }
__device__ __forceinline__ float sigmf(float x) {
    return rcpf(1.0f + ex2f(-1.4426950408889634f * x));
}
__device__ __forceinline__ float tanhf_acc(float x) {
    return fmaf(2.0f, rcpf(1.0f + ex2f(-2.8853900817779268f * x)), -1.0f);
}
__device__ __forceinline__ float act(float v, bool isTanh) {
    return isTanh ? tanhf_acc(v) : sigmf(v);
}

// ---------------- one-time weight transpose ----------------
__global__ void prep_kernel(const float* __restrict__ W_ih, const float* __restrict__ W_hh) {
    int idx = blockIdx.x * blockDim.x + threadIdx.x;   // over 192*512, c fastest
    if (idx >= (NF + H) * G4) return;
    int k = idx / G4;
    int c = idx - k * G4;
    if (k < NF) g_WihT[idx]            = W_ih[c * NF + k];
    else        g_WhhT[(k - NF) * G4 + c] = W_hh[c * H + (k - NF)];
}

// ---------------- prefix: xg[t][b][c] = x[b][t][:] . W_ih[c][:] + b_ih[c] + b_hh[c] ----------------
__global__ void __launch_bounds__(NTHR, 1)
xg_kernel(const float* __restrict__ x,
          const float* __restrict__ b_ih, const float* __restrict__ b_hh)
{
    extern __shared__ float sm[];
    float* Wih = sm;                      // [NF][G4]
    float* xd  = sm + NF * G4;            // [NF][PF_XDPAD] duplicated x rows

    const int tid = threadIdx.x;

    // stage W_ih^T (coalesced)
    {
        const float4* src = (const float4*)g_WihT;
        float4*       dst = (float4*)Wih;
        for (int i = tid; i < NF * G4 / 4; i += NTHR) dst[i] = src[i];
    }

    const int c0 = 2 * (tid & 255);
    const int rg = tid >> 8;              // 0..1
    const int r0 = 4 * rg;

    ull bias2 = pack2(b_ih[c0] + b_hh[c0], b_ih[c0 + 1] + b_hh[c0 + 1]);

    // x loader identity: r = tid>>6 (0..7), f = tid&63
    const int lr = tid >> 6;
    const int lf = tid & 63;

    const int m0 = blockIdx.x * PF_ROWS;  // contiguous (t,b) rows; within one t
    const int t  = m0 >> 10;
    const int bb = m0 & 1023;

    for (int s = 0; s < PF_ROWS / M; ++s) {
        __syncthreads();                  // prev compute done (and W staged on s=0)
        // stage x slab rows bb+8s .. +7, duplicated
        {
            int b = bb + s * M + lr;
            float v = x[((size_t)b * SEQ + t) * NF + lf];
            *(ull*)(xd + lf * PF_XDPAD + 2 * lr) = pack2(v, v);
        }
        __syncthreads();

        ull a0 = bias2, a1 = bias2, a2 = bias2, a3 = bias2;
        #pragma unroll 8
        for (int k = 0; k < NF; ++k) {
            ull w2 = *(const ull*)(Wih + k * G4 + c0);
            ulonglong2 xA = *(const ulonglong2*)(xd + k * PF_XDPAD + 2 * r0);
            ulonglong2 xB = *(const ulonglong2*)(xd + k * PF_XDPAD + 2 * r0 + 4);
            ffma2(a0, xA.x, w2); ffma2(a1, xA.y, w2);
            ffma2(a2, xB.x, w2); ffma2(a3, xB.y, w2);
        }
        float* dst = g_xg + ((size_t)(m0 + s * M + r0)) * G4 + c0;
        *(ull*)(dst + (size_t)0 * G4) = a0;
        *(ull*)(dst + (size_t)1 * G4) = a1;
        *(ull*)(dst + (size_t)2 * G4) = a2;
        *(ull*)(dst + (size_t)3 * G4) = a3;
    }
}

// ---------------- persistent fused LSTM kernel ----------------
__global__ void __launch_bounds__(NTHR, 1)
lstm_kernel(const float* __restrict__ W_out, const float* __restrict__ b_out,
            float* __restrict__ out)
{
    extern __shared__ float sm[];
    float* Wsm  = sm + OFF_WSM;    // [RRES][G4]
    float* xb   = sm + OFF_XB;     // [2][M][G4]
    float* hd   = sm + OFF_HD;     // [H][HDPAD] duplicated h
    float* gbuf = sm + OFF_GBUF;   // [G4][GBPAD]

    const int tid = threadIdx.x;
    const int b0  = blockIdx.x * M;

    // stage resident W_hh rows (coalesced)
    {
        const float4* src = (const float4*)g_WhhT;
        float4*       dst = (float4*)Wsm;
        for (int i = tid; i < RRES * G4 / 4; i += NTHR) dst[i] = src[i];
    }
    for (int i = tid; i < H * HDPAD; i += NTHR) hd[i] = 0.0f;

    // stage xb[0] (t=0): 4096 contiguous floats
    {
        const float4* src = (const float4*)(g_xg + (size_t)b0 * G4);
        float4*       dst = (float4*)xb;
        dst[tid]       = src[tid];
        dst[tid + 512] = src[tid + 512];
    }

    // matvec identity
    const int c0 = 2 * (tid & 255);
    const int rg = tid >> 8;
    const int r0 = 4 * rg;
    const bool isTanh = ((c0 >> 7) == 2);

    // phase-2 identity: h col hc, rows 2a, 2a+1
    const int hc = tid & 127;
    const int aa = tid >> 7;       // 0..3
    const int pr0 = 2 * aa;
    float cst0 = 0.f, cst1 = 0.f;

    __syncthreads();

    const ull* wgbase = (const ull*)(g_WhhT + RRES * G4) + (c0 >> 1);

    for (int t = 0; t < SEQ; ++t) {
        // prefetch next step's xg block (16KB contiguous per CTA)
        float4 p0, p1;
        const bool doPre = (t + 1 < SEQ);
        if (doPre) {
            const float4* src = (const float4*)(g_xg + ((size_t)(t + 1) * BATCH + b0) * G4);
            p0 = src[tid];
            p1 = src[tid + 512];
        }

        const float* xcur = xb + (t & 1) * (M * G4);

        // init accumulators from xg (bias folded)
        ull a0 = *(const ull*)(xcur + (r0 + 0) * G4 + c0);
        ull a1 = *(const ull*)(xcur + (r0 + 1) * G4 + c0);
        ull a2 = *(const ull*)(xcur + (r0 + 2) * G4 + c0);
        ull a3 = *(const ull*)(xcur + (r0 + 3) * G4 + c0);

        // resident part
        #pragma unroll 4
        for (int k = 0; k < RRES; ++k) {
            ull w2 = *(const ull*)(Wsm + k * G4 + c0);
            ulonglong2 hA = *(const ulonglong2*)(hd + k * HDPAD + 2 * r0);
            ulonglong2 hB = *(const ulonglong2*)(hd + k * HDPAD + 2 * r0 + 4);
            ffma2(a0, hA.x, w2); ffma2(a1, hA.y, w2);
            ffma2(a2, hB.x, w2); ffma2(a3, hB.y, w2);
        }
        // streamed part (L2-resident weights)
        {
            const ull* wg = wgbase;
            #pragma unroll 4
            for (int k = RRES; k < H; ++k) {
                ull w2 = __ldg(wg); wg += (G4 / 2);
                ulonglong2 hA = *(const ulonglong2*)(hd + k * HDPAD + 2 * r0);
                ulonglong2 hB = *(const ulonglong2*)(hd + k * HDPAD + 2 * r0 + 4);
                ffma2(a0, hA.x, w2); ffma2(a1, hA.y, w2);
                ffma2(a2, hB.x, w2); ffma2(a3, hB.y, w2);
            }
        }

        // activations -> gbuf
        {
            float v0, v1;
            float* gb0 = gbuf + c0 * GBPAD + r0;
            float* gb1 = gbuf + (c0 + 1) * GBPAD + r0;
            unpack2(a0, v0, v1); gb0[0] = act(v0, isTanh); gb1[0] = act(v1, isTanh);
            unpack2(a1, v0, v1); gb0[1] = act(v0, isTanh); gb1[1] = act(v1, isTanh);
            unpack2(a2, v0, v1); gb0[2] = act(v0, isTanh); gb1[2] = act(v1, isTanh);
            unpack2(a3, v0, v1); gb0[3] = act(v0, isTanh); gb1[3] = act(v1, isTanh);
        }
        __syncthreads();

        // phase 2: state update for (hc, rows pr0, pr0+1)
        {
            const float* gi = gbuf + hc * GBPAD;
            const float* gf = gi + 128 * GBPAD;
            const float* gg = gi + 256 * GBPAD;
            const float* go = gi + 384 * GBPAD;

            float i0 = gi[pr0],     f0 = gf[pr0],     g0 = gg[pr0],     o0 = go[pr0];
            float i1 = gi[pr0 + 1], f1 = gf[pr0 + 1], g1 = gg[pr0 + 1], o1 = go[pr0 + 1];
            cst0 = fmaf(f0, cst0, i0 * g0);
            cst1 = fmaf(f1, cst1, i1 * g1);
            float h0 = o0 * tanhf_acc(cst0);
            float h1 = o1 * tanhf_acc(cst1);
            *(ull*)(hd + hc * HDPAD + 2 * pr0)     = pack2(h0, h0);
            *(ull*)(hd + hc * HDPAD + 2 * pr0 + 2) = pack2(h1, h1);

            if (doPre) {
                float4* dst = (float4*)(xb + ((t + 1) & 1) * (M * G4));
                dst[tid]       = p0;
                dst[tid + 512] = p1;
            }
        }
        __syncthreads();
    }

    // output projection: out[b0+r][oc] = h_r . W_out[oc,:] + b_out[oc]
    {
        const int oc = hc;
        float acc0 = b_out[oc], acc1 = acc0;
        const float* wrow = W_out + oc * H;
        #pragma unroll 8
        for (int k = 0; k < H; ++k) {
            float w  = wrow[k];
            float h0 = hd[k * HDPAD + 2 * pr0];
            float h1 = hd[k * HDPAD + 2 * pr0 + 2];
            acc0 = fmaf(w, h0, acc0);
            acc1 = fmaf(w, h1, acc1);
        }
        out[(size_t)(b0 + pr0)     * NOUT + oc] = acc0;
        out[(size_t)(b0 + pr0 + 1) * NOUT + oc] = acc1;
    }
}

extern "C" void kernel_launch(void* const* d_in, const int* in_sizes, int n_in,
                              void* d_out, int out_size)
{
    const float* x     = (const float*)d_in[0];
    const float* W_ih  = (const float*)d_in[1];
    const float* W_hh  = (const float*)d_in[2];
    const float* b_ih  = (const float*)d_in[3];
    const float* b_hh  = (const float*)d_in[4];
    const float* W_out = (const float*)d_in[5];
    const float* b_out = (const float*)d_in[6];
    float* out = (float*)d_out;

    prep_kernel<<<((NF + H) * G4 + 255) / 256, 256>>>(W_ih, W_hh);

    cudaFuncSetAttribute(xg_kernel,
                         cudaFuncAttributeMaxDynamicSharedMemorySize, PF_SMEM_BYTES);
    xg_kernel<<<PF_NCTA, NTHR, PF_SMEM_BYTES>>>(x, b_ih, b_hh);

    cudaFuncSetAttribute(lstm_kernel,
                         cudaFuncAttributeMaxDynamicSharedMemorySize, SMEM_BYTES);
    lstm_kernel<<<NCTA, NTHR, SMEM_BYTES>>>(W_out, b_out, out);
}

// round 5
// speedup vs baseline: 1.6977x; 1.6977x over previous
#include <cuda_runtime.h>
#include <cstdint>

// Problem constants
#define BATCH 1024
#define SEQ   512
#define NF    64
#define H     128
#define G4    512
#define NOUT  128

// Kernel config
#define M     8              // batch rows per CTA
#define NCTA  128
#define NTHR  512
#define RES   26             // W_hh rows resident in smem (rest streamed from L2)

// smem layout (floats)
#define OFF_WIH   0                         // [64][512]
#define OFF_WHH   (64 * G4)                 // [RES][512] rows 0..RES-1
#define OFF_XD    (OFF_WHH + RES * G4)      // [64][8]  plain x, row-major f
#define OFF_HD    (OFF_XD + NF * M)         // [128][8] plain h
#define OFF_GB    (OFF_HD + H * M)          // [512][9] gates
#define OFF_PART  (OFF_GB + G4 * 9)         // [8][256] ull partials (4096 fl)
#define SMEM_FLOATS (OFF_PART + 8 * 256 * 2)
#define SMEM_BYTES  (SMEM_FLOATS * 4)       // 225280

typedef unsigned long long ull;

// transposed weights (built once per launch)
__device__ float g_WihT[NF * G4];     // [f][c]
__device__ float g_WhhT[H * G4];      // [k][c]
__device__ float g_WoutT[H * NOUT];   // [k][oc]

// ---------------- packed f32x2 helpers ----------------
__device__ __forceinline__ void ffma2(ull& acc, ull a, ull b) {
    asm("fma.rn.f32x2 %0, %1, %2, %0;" : "+l"(acc) : "l"(a), "l"(b));
}
__device__ __forceinline__ ull fadd2(ull a, ull b) {
    ull r; asm("add.rn.f32x2 %0, %1, %2;" : "=l"(r) : "l"(a), "l"(b)); return r;
}
__device__ __forceinline__ ull pack2(float lo, float hi) {
    ull r; asm("mov.b64 %0, {%1, %2};" : "=l"(r) : "f"(lo), "f"(hi)); return r;
}
__device__ __forceinline__ void unpack2(ull v, float& lo, float& hi) {
    asm("mov.b64 {%0, %1}, %2;" : "=f"(lo), "=f"(hi) : "l"(v));
}
// from packed (w0,w1) make (w0,w0) and (w1,w1)
__device__ __forceinline__ void dup2(ull w2, ull& d0, ull& d1) {
    asm("{\n\t"
        ".reg .f32 w0, w1;\n\t"
        "mov.b64 {w0, w1}, %2;\n\t"
        "mov.b64 %0, {w0, w0};\n\t"
        "mov.b64 %1, {w1, w1};\n\t"
        "}" : "=l"(d0), "=l"(d1) : "l"(w2));
}

// ---------------- activations ----------------
__device__ __forceinline__ float ex2f(float x) { float r; asm("ex2.approx.f32 %0, %1;" : "=f"(r) : "f"(x)); return r; }
__device__ __forceinline__ float rcpf(float x) { float r; asm("rcp.approx.f32 %0, %1;" : "=f"(r) : "f"(x)); return r; }
__device__ __forceinline__ float sigmf(float x) {
    return rcpf(1.0f + ex2f(-1.4426950408889634f * x));
}
__device__ __forceinline__ float tanhf_acc(float x) {
    return fmaf(2.0f, rcpf(1.0f + ex2f(-2.8853900817779268f * x)), -1.0f);
}
__device__ __forceinline__ float act(float v, bool isTanh) {
    return isTanh ? tanhf_acc(v) : sigmf(v);
}

// ---------------- one-time weight transpose ----------------
__global__ void prep_kernel(const float* __restrict__ W_ih,
                            const float* __restrict__ W_hh,
                            const float* __restrict__ W_out) {
    int idx = blockIdx.x * blockDim.x + threadIdx.x;
    if (idx < (NF + H) * G4) {
        int k = idx / G4;
        int c = idx - k * G4;
        if (k < NF) g_WihT[idx]               = W_ih[c * NF + k];
        else        g_WhhT[(k - NF) * G4 + c] = W_hh[c * H + (k - NF)];
    } else {
        int j = idx - (NF + H) * G4;
        if (j < H * NOUT) {
            int k = j >> 7, oc = j & 127;
            g_WoutT[k * NOUT + oc] = W_out[oc * H + k];
        }
    }
}

// matvec micro-step: acc[c][rp] += rowpair * dup(w_c)
#define STEPK(W2, HSRC)                                                 \
    do {                                                                \
        ull d0, d1; dup2((W2), d0, d1);                                 \
        ulonglong2 hA = *(const ulonglong2*)(HSRC);                     \
        ulonglong2 hB = *(const ulonglong2*)((HSRC) + 4);               \
        ffma2(a00, hA.x, d0); ffma2(a01, hA.y, d0);                     \
        ffma2(a02, hB.x, d0); ffma2(a03, hB.y, d0);                     \
        ffma2(a10, hA.x, d1); ffma2(a11, hA.y, d1);                     \
        ffma2(a12, hB.x, d1); ffma2(a13, hB.y, d1);                     \
    } while (0)

// ---------------- persistent fused LSTM kernel ----------------
__global__ void __launch_bounds__(NTHR, 1)
lstm_kernel(const float* __restrict__ x,
            const float* __restrict__ b_ih, const float* __restrict__ b_hh,
            const float* __restrict__ b_out,
            float* __restrict__ out)
{
    extern __shared__ float sm[];
    float* Wih  = sm + OFF_WIH;
    float* Whh  = sm + OFF_WHH;
    float* xd   = sm + OFF_XD;
    float* hd   = sm + OFF_HD;
    float* gbuf = sm + OFF_GB;
    ull*   part = (ull*)(sm + OFF_PART);

    const int tid = threadIdx.x;
    const int b0  = blockIdx.x * M;

    const int cp = tid & 255;       // col-pair -> cols c0, c0+1
    const int c0 = 2 * cp;
    const int kg = tid >> 8;        // 0: x + h[0,32), 1: h[32,128)

    // ---- stage resident weights ----
    {
        const float4* s = (const float4*)g_WihT;
        float4*       d = (float4*)Wih;
        #pragma unroll
        for (int i = 0; i < (NF * G4 / 4) / NTHR; ++i) d[tid + i * NTHR] = s[tid + i * NTHR];
    }
    {
        const float4* s = (const float4*)g_WhhT;
        float4*       d = (float4*)Whh;
        for (int i = tid; i < RES * G4 / 4; i += NTHR) d[i] = s[i];
    }
    for (int i = tid; i < H * M; i += NTHR) hd[i] = 0.0f;

    // x loader identity: one value/thread: f = tid&63, r = tid>>6
    const int lf = tid & 63, lr = tid >> 6;
    const float* xp = x + ((size_t)(b0 + lr) * SEQ) * NF + lf;
    xd[lf * M + lr] = xp[0];

    // kg0 bias init
    const ull bias0 = (kg == 0) ? pack2(b_ih[c0] + b_hh[c0], b_ih[c0] + b_hh[c0]) : 0ull;
    const ull bias1 = (kg == 0) ? pack2(b_ih[c0 + 1] + b_hh[c0 + 1], b_ih[c0 + 1] + b_hh[c0 + 1]) : 0ull;
    const bool isT = ((c0 >> 7) == 2);   // gate g (cols 256..383)

    // phase-2 identity
    const int hc = tid & 127;
    const int aa = (tid >> 7) & 3;       // rows 2aa, 2aa+1
    float cst0 = 0.f, cst1 = 0.f;

    const ull* wStream = (const ull*)(g_WhhT + 32 * G4) + cp;  // kg1 stream base

    __syncthreads();

    for (int t = 0; t < SEQ; ++t) {
        // prefetch next x value (hidden under matvec)
        float xpre = 0.f;
        const bool doPre = (t + 1 < SEQ);
        if (doPre) xpre = xp[(size_t)(t + 1) * NF];

        ull a00 = bias0, a01 = bias0, a02 = bias0, a03 = bias0;
        ull a10 = bias1, a11 = bias1, a12 = bias1, a13 = bias1;

        if (kg == 0) {
            // x-part: 64 k, weights in smem
            #pragma unroll 16
            for (int j = 0; j < NF; ++j) {
                ull w2 = *(const ull*)(Wih + j * G4 + c0);
                STEPK(w2, xd + j * M);
            }
            // h-part rows [0,RES): smem
            #pragma unroll
            for (int k = 0; k < RES; ++k) {
                ull w2 = *(const ull*)(Whh + k * G4 + c0);
                STEPK(w2, hd + k * M);
            }
            // h-part rows [RES,32): L2 stream
            #pragma unroll
            for (int k = RES; k < 32; ++k) {
                ull w2 = __ldg((const ull*)(g_WhhT + k * G4) + cp);
                STEPK(w2, hd + k * M);
            }
        } else {
            // h-part rows [32,128): L2 stream
            const ull* wg = wStream;
            #pragma unroll 16
            for (int k = 32; k < H; ++k) {
                ull w2 = __ldg(wg); wg += (G4 / 2);
                STEPK(w2, hd + k * M);
            }
        }

        if (kg == 1) {
            ull* pb = part + cp;
            pb[0 * 256] = a00; pb[1 * 256] = a01; pb[2 * 256] = a02; pb[3 * 256] = a03;
            pb[4 * 256] = a10; pb[5 * 256] = a11; pb[6 * 256] = a12; pb[7 * 256] = a13;
        }
        __syncthreads();   // S1: partials visible; all xd/hd reads done

        if (kg == 0) {
            const ull* pb = part + cp;
            a00 = fadd2(a00, pb[0 * 256]); a01 = fadd2(a01, pb[1 * 256]);
            a02 = fadd2(a02, pb[2 * 256]); a03 = fadd2(a03, pb[3 * 256]);
            a10 = fadd2(a10, pb[4 * 256]); a11 = fadd2(a11, pb[5 * 256]);
            a12 = fadd2(a12, pb[6 * 256]); a13 = fadd2(a13, pb[7 * 256]);

            float v0, v1;
            float* g0 = gbuf + c0 * 9;
            float* g1 = g0 + 9;
            unpack2(a00, v0, v1); g0[0] = act(v0, isT); g0[1] = act(v1, isT);
            unpack2(a01, v0, v1); g0[2] = act(v0, isT); g0[3] = act(v1, isT);
            unpack2(a02, v0, v1); g0[4] = act(v0, isT); g0[5] = act(v1, isT);
            unpack2(a03, v0, v1); g0[6] = act(v0, isT); g0[7] = act(v1, isT);
            unpack2(a10, v0, v1); g1[0] = act(v0, isT); g1[1] = act(v1, isT);
            unpack2(a11, v0, v1); g1[2] = act(v0, isT); g1[3] = act(v1, isT);
            unpack2(a12, v0, v1); g1[4] = act(v0, isT); g1[5] = act(v1, isT);
            unpack2(a13, v0, v1); g1[6] = act(v0, isT); g1[7] = act(v1, isT);
        }
        // stage next x (xd fully consumed before S1)
        if (doPre) xd[lf * M + lr] = xpre;

        __syncthreads();   // S2: gates + xd ready

        // phase 2: state update for (hc, rows 2aa, 2aa+1)
        {
            const float* gi = gbuf + hc * 9;
            const float* gf = gi + 128 * 9;
            const float* gg = gi + 256 * 9;
            const float* go = gi + 384 * 9;
            float i0 = gi[2 * aa],     f0 = gf[2 * aa],     gv0 = gg[2 * aa],     o0 = go[2 * aa];
            float i1 = gi[2 * aa + 1], f1 = gf[2 * aa + 1], gv1 = gg[2 * aa + 1], o1 = go[2 * aa + 1];
            cst0 = fmaf(f0, cst0, i0 * gv0);
            cst1 = fmaf(f1, cst1, i1 * gv1);
            hd[hc * M + 2 * aa]     = o0 * tanhf_acc(cst0);
            hd[hc * M + 2 * aa + 1] = o1 * tanhf_acc(cst1);
        }
        __syncthreads();   // S3: hd(t) ready for next matvec
    }

    // ---- output projection: thread (oc, rows rr, rr+4) ----
    {
        const int oc = tid & 127;
        const int rr = tid >> 7;
        float acc0 = b_out[oc], acc1 = acc0;
        const float* wt = g_WoutT + oc;
        #pragma unroll 8
        for (int k = 0; k < H; ++k) {
            float w = __ldg(wt + k * NOUT);
            acc0 = fmaf(w, hd[k * M + rr], acc0);
            acc1 = fmaf(w, hd[k * M + rr + 4], acc1);
        }
        out[(size_t)(b0 + rr) * NOUT + oc]     = acc0;
        out[(size_t)(b0 + rr + 4) * NOUT + oc] = acc1;
    }
}

extern "C" void kernel_launch(void* const* d_in, const int* in_sizes, int n_in,
                              void* d_out, int out_size)
{
    const float* x     = (const float*)d_in[0];
    const float* W_ih  = (const float*)d_in[1];
    const float* W_hh  = (const float*)d_in[2];
    const float* b_ih  = (const float*)d_in[3];
    const float* b_hh  = (const float*)d_in[4];
    const float* W_out = (const float*)d_in[5];
    const float* b_out = (const float*)d_in[6];
    float* out = (float*)d_out;

    const int prep_n = (NF + H) * G4 + H * NOUT;
    prep_kernel<<<(prep_n + 255) / 256, 256>>>(W_ih, W_hh, W_out);

    cudaFuncSetAttribute(lstm_kernel,
                         cudaFuncAttributeMaxDynamicSharedMemorySize, SMEM_BYTES);
    lstm_kernel<<<NCTA, NTHR, SMEM_BYTES>>>(x, b_ih, b_hh, b_out, out);
}